// round 11
// baseline (speedup 1.0000x reference)
#include <cuda_runtime.h>
#include <cuda_fp16.h>
#include <math.h>
#include <stdint.h>

// Flash attention w/ bias + causal, fp32 I/O, fp16 mma.sync (m16n8k16).
// 2 CTAs/SM, 64KB smem, 128-reg cap. Double-buffered K/V with ONE barrier/tile;
// tile n+1 staged between softmax and PV of tile n (stall covered by MMA phases),
// with prefetch.global.L2 issued a full phase ahead.
// QK = Qh*K + Ql*K ; PV = Ph*V + Pl*V (P hi/lo fp16 from S-regs).

#define SEQ 1024
#define BM  128
#define BKT 64

#define SM_QH  0u
#define SM_QL  16384u
#define SM_KV  32768u
#define KVSZ   16384u
#define KV_K   0u
#define KV_V   8192u
#define SM_TOTAL 65536

static __device__ __forceinline__ uint32_t smem_u32(const void* p) {
    uint32_t a;
    asm("{ .reg .u64 t; cvta.to.shared.u64 t, %1; cvt.u32.u64 %0, t; }" : "=r"(a) : "l"(p));
    return a;
}
static __device__ __forceinline__ uint32_t swz(int row, int chunk) {
    return (uint32_t)(row * 128 + ((chunk ^ (row & 7)) << 4));
}
static __device__ __forceinline__ uint32_t hpair(float a, float b) {
    __half2 t = __floats2half2_rn(a, b);
    return *reinterpret_cast<uint32_t*>(&t);
}
static __device__ __forceinline__ void pref_l2(const void* p) {
    asm volatile("prefetch.global.L2 [%0];" :: "l"(p));
}
static __device__ __forceinline__ void ldsm4(uint32_t r[4], uint32_t addr) {
    asm volatile("ldmatrix.sync.aligned.m8n8.x4.shared.b16 {%0,%1,%2,%3}, [%4];"
                 : "=r"(r[0]), "=r"(r[1]), "=r"(r[2]), "=r"(r[3]) : "r"(addr));
}
static __device__ __forceinline__ void ldsm4t(uint32_t r[4], uint32_t addr) {
    asm volatile("ldmatrix.sync.aligned.m8n8.x4.trans.shared.b16 {%0,%1,%2,%3}, [%4];"
                 : "=r"(r[0]), "=r"(r[1]), "=r"(r[2]), "=r"(r[3]) : "r"(addr));
}
static __device__ __forceinline__ void lda(uint32_t a[4], uint32_t tb, int row0, int kk, int lane) {
    int sel = lane >> 3;
    int row = row0 + (lane & 7) + ((sel & 1) << 3);
    int ch  = kk * 2 + (sel >> 1);
    ldsm4(a, tb + swz(row, ch));
}
static __device__ __forceinline__ void ldb(uint32_t b[4], uint32_t tb, int n0, int kk, int lane) {
    int sel = lane >> 3;
    int row = n0 + ((sel >> 1) << 3) + (lane & 7);
    int ch  = kk * 2 + (sel & 1);
    ldsm4(b, tb + swz(row, ch));
}
static __device__ __forceinline__ void ldbT(uint32_t b[4], uint32_t tb, int kk, int nb2, int lane) {
    int sel = lane >> 3;
    int row = kk * 16 + ((sel & 1) << 3) + (lane & 7);
    int ch  = nb2 * 2 + (sel >> 1);
    ldsm4t(b, tb + swz(row, ch));
}
static __device__ __forceinline__ void mmaf16(float c[4], const uint32_t a[4], uint32_t b0, uint32_t b1) {
    asm volatile("mma.sync.aligned.m16n8k16.row.col.f32.f16.f16.f32 "
                 "{%0,%1,%2,%3}, {%4,%5,%6,%7}, {%8,%9}, {%0,%1,%2,%3};"
                 : "+f"(c[0]), "+f"(c[1]), "+f"(c[2]), "+f"(c[3])
                 : "r"(a[0]), "r"(a[1]), "r"(a[2]), "r"(a[3]), "r"(b0), "r"(b1));
}

__global__ __launch_bounds__(256, 2)
void attn_f16_kernel(const float* __restrict__ q,
                     const float* __restrict__ k,
                     const float* __restrict__ v,
                     const float* __restrict__ bias,
                     float* __restrict__ out)
{
    extern __shared__ char smem[];
    const uint32_t sb = smem_u32(smem);
    const int tid  = threadIdx.x;
    const int wid  = tid >> 5;
    const int lane = tid & 31;
    const int qd   = lane & 3;

    const int m  = 7 - (int)(blockIdx.x >> 6);   // heavy CTAs first
    const int bh = (int)(blockIdx.x & 63);

    const float* kbase = k + (size_t)bh * SEQ * 64;
    const float* vbase = v + (size_t)bh * SEQ * 64;

    // per-thread staging coords (4 rows x one 16B chunk)
    const int sd4 = (tid & 15) * 4;
    int srow[4]; uint32_t soff[4];
    #pragma unroll
    for (int i = 0; i < 4; ++i) {
        srow[i] = (tid + i * 256) >> 4;
        soff[i] = swz(srow[i], sd4 >> 3) + (uint32_t)((sd4 & 7) * 2);
    }

    // ---- prologue: stage Q (scaled, fp16 hi/lo split) ----
    const float* qp = q + ((size_t)bh * SEQ + (size_t)m * BM) * 64;
    #pragma unroll
    for (int i = 0; i < 8; ++i) {
        int lin = tid + i * 256;
        int row = lin >> 4;
        int d4  = (lin & 15) * 4;
        float4 v4 = *reinterpret_cast<const float4*>(qp + row * 64 + d4);
        float xs[4] = {v4.x * 0.125f, v4.y * 0.125f, v4.z * 0.125f, v4.w * 0.125f};
        float h[4], l[4];
        #pragma unroll
        for (int e = 0; e < 4; ++e) {
            __half hh = __float2half_rn(xs[e]);
            h[e] = __half2float(hh);
            l[e] = xs[e] - h[e];
        }
        uint32_t off = swz(row, d4 >> 3) + (uint32_t)((d4 & 7) * 2);
        *reinterpret_cast<uint2*>(smem + SM_QH + off) = make_uint2(hpair(h[0], h[1]), hpair(h[2], h[3]));
        *reinterpret_cast<uint2*>(smem + SM_QL + off) = make_uint2(hpair(l[0], l[1]), hpair(l[2], l[3]));
    }

    // ---- prologue: stage K/V tile 0 into buffer 0 ----
    #pragma unroll
    for (int i = 0; i < 4; ++i) {
        float4 kv = *reinterpret_cast<const float4*>(kbase + srow[i] * 64 + sd4);
        *reinterpret_cast<uint2*>(smem + SM_KV + KV_K + soff[i]) =
            make_uint2(hpair(kv.x, kv.y), hpair(kv.z, kv.w));
        float4 vv = *reinterpret_cast<const float4*>(vbase + srow[i] * 64 + sd4);
        *reinterpret_cast<uint2*>(smem + SM_KV + KV_V + soff[i]) =
            make_uint2(hpair(vv.x, vv.y), hpair(vv.z, vv.w));
    }

    const int wr0 = wid * 16;
    const int gra = m * BM + wr0 + (lane >> 2);
    const int grb = gra + 8;

    float s[8][4];
    float o[8][4];
    #pragma unroll
    for (int nb = 0; nb < 8; ++nb)
        #pragma unroll
        for (int e = 0; e < 4; ++e) o[nb][e] = 0.f;
    float m_a = -INFINITY, m_b = -INFINITY, l_a = 0.f, l_b = 0.f;

    const int ntiles = 2 * m + 2;
    const int wlast  = m * BM + wr0 + 15;

    for (int n = 0; n < ntiles; ++n) {
        const bool havenext = (n + 1 < ntiles);
        const float* kpn = kbase + (size_t)(n + 1) * BKT * 64;
        const float* vpn = vbase + (size_t)(n + 1) * BKT * 64;

        // L2 prefetch for tile n+1 (consumed by the stage block ~1k cycles later)
        if (havenext) {
            #pragma unroll
            for (int i = 0; i < 4; ++i) {
                pref_l2(kpn + srow[i] * 64 + sd4);
                pref_l2(vpn + srow[i] * 64 + sd4);
            }
        }

        __syncthreads();   // single barrier: stage(n) visible, buffer (n+1)&1 free

        const uint32_t kvb = SM_KV + (uint32_t)(n & 1) * KVSZ;
        const uint32_t KB = sb + kvb + KV_K;
        const uint32_t VB = sb + kvb + KV_V;
        const bool active = (n * BKT <= wlast);

        if (active) {
            // bias prefetch (hides under QK MMAs)
            float2 ba[8], bb[8];
            {
                const float* bpa = bias + ((size_t)bh * SEQ + gra) * SEQ + (size_t)n * BKT;
                const float* bpb = bias + ((size_t)bh * SEQ + grb) * SEQ + (size_t)n * BKT;
                #pragma unroll
                for (int nb = 0; nb < 8; ++nb) {
                    ba[nb] = *reinterpret_cast<const float2*>(bpa + nb * 8 + 2 * qd);
                    bb[nb] = *reinterpret_cast<const float2*>(bpb + nb * 8 + 2 * qd);
                }
            }

            // ---- S = Qh*K + Ql*K ----
            #pragma unroll
            for (int nb = 0; nb < 8; ++nb)
                #pragma unroll
                for (int e = 0; e < 4; ++e) s[nb][e] = 0.f;
            #pragma unroll
            for (int kk = 0; kk < 4; ++kk) {
                uint32_t aqh[4], aql[4];
                lda(aqh, sb + SM_QH, wr0, kk, lane);
                lda(aql, sb + SM_QL, wr0, kk, lane);
                #pragma unroll
                for (int nb2 = 0; nb2 < 4; ++nb2) {
                    uint32_t bk[4];
                    ldb(bk, KB, nb2 * 16, kk, lane);
                    mmaf16(s[2 * nb2],     aqh, bk[0], bk[1]);
                    mmaf16(s[2 * nb2 + 1], aqh, bk[2], bk[3]);
                    mmaf16(s[2 * nb2],     aql, bk[0], bk[1]);
                    mmaf16(s[2 * nb2 + 1], aql, bk[2], bk[3]);
                }
            }

            // ---- bias + causal mask ----
            const int c00 = n * BKT + 2 * qd;
            #pragma unroll
            for (int nb = 0; nb < 8; ++nb) {
                int c0 = c00 + nb * 8, c1 = c0 + 1;
                s[nb][0] = (c0 <= gra) ? s[nb][0] + ba[nb].x : -INFINITY;
                s[nb][1] = (c1 <= gra) ? s[nb][1] + ba[nb].y : -INFINITY;
                s[nb][2] = (c0 <= grb) ? s[nb][2] + bb[nb].x : -INFINITY;
                s[nb][3] = (c1 <= grb) ? s[nb][3] + bb[nb].y : -INFINITY;
            }

            // ---- online softmax ----
            float tma = -INFINITY, tmb = -INFINITY;
            #pragma unroll
            for (int nb = 0; nb < 8; ++nb) {
                tma = fmaxf(tma, fmaxf(s[nb][0], s[nb][1]));
                tmb = fmaxf(tmb, fmaxf(s[nb][2], s[nb][3]));
            }
            tma = fmaxf(tma, __shfl_xor_sync(0xffffffffu, tma, 1));
            tma = fmaxf(tma, __shfl_xor_sync(0xffffffffu, tma, 2));
            tmb = fmaxf(tmb, __shfl_xor_sync(0xffffffffu, tmb, 1));
            tmb = fmaxf(tmb, __shfl_xor_sync(0xffffffffu, tmb, 2));

            float mna = fmaxf(m_a, tma), mnb = fmaxf(m_b, tmb);
            float ca = __expf(m_a - mna), cb = __expf(m_b - mnb);
            m_a = mna; m_b = mnb;

            float pa = 0.f, pb = 0.f;
            #pragma unroll
            for (int nb = 0; nb < 8; ++nb) {
                float p0 = __expf(s[nb][0] - mna);
                float p1 = __expf(s[nb][1] - mna);
                float p2 = __expf(s[nb][2] - mnb);
                float p3 = __expf(s[nb][3] - mnb);
                s[nb][0] = p0; s[nb][1] = p1; s[nb][2] = p2; s[nb][3] = p3;
                pa += p0 + p1; pb += p2 + p3;
            }
            pa += __shfl_xor_sync(0xffffffffu, pa, 1);
            pa += __shfl_xor_sync(0xffffffffu, pa, 2);
            pb += __shfl_xor_sync(0xffffffffu, pb, 1);
            pb += __shfl_xor_sync(0xffffffffu, pb, 2);
            l_a = l_a * ca + pa;
            l_b = l_b * cb + pb;
            #pragma unroll
            for (int nb = 0; nb < 8; ++nb) {
                o[nb][0] *= ca; o[nb][1] *= ca;
                o[nb][2] *= cb; o[nb][3] *= cb;
            }
        }

        // ---- stage tile n+1 into buffer (n+1)&1 (stall covered by QK/PV of peers) ----
        if (havenext) {
            char* kvn = smem + SM_KV + (size_t)((n + 1) & 1) * KVSZ;
            #pragma unroll
            for (int i = 0; i < 4; ++i) {
                float4 kv = *reinterpret_cast<const float4*>(kpn + srow[i] * 64 + sd4);
                *reinterpret_cast<uint2*>(kvn + KV_K + soff[i]) =
                    make_uint2(hpair(kv.x, kv.y), hpair(kv.z, kv.w));
                float4 vv = *reinterpret_cast<const float4*>(vpn + srow[i] * 64 + sd4);
                *reinterpret_cast<uint2*>(kvn + KV_V + soff[i]) =
                    make_uint2(hpair(vv.x, vv.y), hpair(vv.z, vv.w));
            }
        }

        if (active) {
            // ---- O += Ph*V + Pl*V (P hi/lo fp16 straight from S regs) ----
            #pragma unroll
            for (int kk = 0; kk < 4; ++kk) {
                uint32_t aph[4], apl[4];
                #pragma unroll
                for (int half = 0; half < 2; ++half) {
                    const float* sp = s[2 * kk + half];
                    float h[4], l[4];
                    #pragma unroll
                    for (int e = 0; e < 4; ++e) {
                        __half hh = __float2half_rn(sp[e]);
                        h[e] = __half2float(hh);
                        l[e] = sp[e] - h[e];
                    }
                    aph[2 * half]     = hpair(h[0], h[1]);
                    aph[2 * half + 1] = hpair(h[2], h[3]);
                    apl[2 * half]     = hpair(l[0], l[1]);
                    apl[2 * half + 1] = hpair(l[2], l[3]);
                }
                #pragma unroll
                for (int nb2 = 0; nb2 < 4; ++nb2) {
                    uint32_t bv[4];
                    ldbT(bv, VB, kk, nb2, lane);
                    mmaf16(o[2 * nb2],     aph, bv[0], bv[1]);
                    mmaf16(o[2 * nb2 + 1], aph, bv[2], bv[3]);
                    mmaf16(o[2 * nb2],     apl, bv[0], bv[1]);
                    mmaf16(o[2 * nb2 + 1], apl, bv[2], bv[3]);
                }
            }
        }
    }

    // ---- epilogue ----
    const float ia = 1.f / l_a, ib = 1.f / l_b;
    float* opa = out + ((size_t)bh * SEQ + gra) * 64;
    float* opb = out + ((size_t)bh * SEQ + grb) * 64;
    #pragma unroll
    for (int nb = 0; nb < 8; ++nb) {
        int col = nb * 8 + 2 * qd;
        *reinterpret_cast<float2*>(opa + col) = make_float2(o[nb][0] * ia, o[nb][1] * ia);
        *reinterpret_cast<float2*>(opb + col) = make_float2(o[nb][2] * ib, o[nb][3] * ib);
    }
}

extern "C" void kernel_launch(void* const* d_in, const int* in_sizes, int n_in,
                              void* d_out, int out_size)
{
    const float* q    = (const float*)d_in[0];
    const float* k    = (const float*)d_in[1];
    const float* v    = (const float*)d_in[2];
    const float* bias = (const float*)d_in[3];
    float* out = (float*)d_out;

    cudaFuncSetAttribute(attn_f16_kernel,
                         cudaFuncAttributeMaxDynamicSharedMemorySize, SM_TOTAL);
    attn_f16_kernel<<<512, 256, SM_TOTAL>>>(q, k, v, bias, out);
}

// round 12
// speedup vs baseline: 1.4367x; 1.4367x over previous
#include <cuda_runtime.h>
#include <cuda_fp16.h>
#include <math.h>
#include <stdint.h>

// Flash attention w/ bias + causal, fp32 I/O, fp16 mma.sync (m16n8k16).
// 2 CTAs/SM, 96KB smem, 128-reg cap. K/V staged in 128-key super-tiles
// (double-buffered, ONE barrier per super-tile); compute runs two 64-key
// halves per buffer. QK = Qh*K + Ql*K ; PV = Ph*V + Pl*V (P from S-regs).

#define SEQ 1024
#define BM  128
#define BKT 64

// smem: Q hi/lo (16KB each), two K/V buffers of 32KB (K 16KB + V 16KB, 128 rows)
#define SM_QH  0u
#define SM_QL  16384u
#define SM_KV  32768u
#define KVSZ   32768u
#define KV_K   0u
#define KV_V   16384u
#define SM_TOTAL 98304

static __device__ __forceinline__ uint32_t smem_u32(const void* p) {
    uint32_t a;
    asm("{ .reg .u64 t; cvta.to.shared.u64 t, %1; cvt.u32.u64 %0, t; }" : "=r"(a) : "l"(p));
    return a;
}
// row stride 128B (64 fp16), 16B chunks XOR-swizzled by row
static __device__ __forceinline__ uint32_t swz(int row, int chunk) {
    return (uint32_t)(row * 128 + ((chunk ^ (row & 7)) << 4));
}
static __device__ __forceinline__ uint32_t hpair(float a, float b) {
    __half2 t = __floats2half2_rn(a, b);
    return *reinterpret_cast<uint32_t*>(&t);
}
static __device__ __forceinline__ void ldsm4(uint32_t r[4], uint32_t addr) {
    asm volatile("ldmatrix.sync.aligned.m8n8.x4.shared.b16 {%0,%1,%2,%3}, [%4];"
                 : "=r"(r[0]), "=r"(r[1]), "=r"(r[2]), "=r"(r[3]) : "r"(addr));
}
static __device__ __forceinline__ void ldsm4t(uint32_t r[4], uint32_t addr) {
    asm volatile("ldmatrix.sync.aligned.m8n8.x4.trans.shared.b16 {%0,%1,%2,%3}, [%4];"
                 : "=r"(r[0]), "=r"(r[1]), "=r"(r[2]), "=r"(r[3]) : "r"(addr));
}
static __device__ __forceinline__ void lda(uint32_t a[4], uint32_t tb, int row0, int kk, int lane) {
    int sel = lane >> 3;
    int row = row0 + (lane & 7) + ((sel & 1) << 3);
    int ch  = kk * 2 + (sel >> 1);
    ldsm4(a, tb + swz(row, ch));
}
static __device__ __forceinline__ void ldb(uint32_t b[4], uint32_t tb, int n0, int kk, int lane) {
    int sel = lane >> 3;
    int row = n0 + ((sel >> 1) << 3) + (lane & 7);
    int ch  = kk * 2 + (sel & 1);
    ldsm4(b, tb + swz(row, ch));
}
static __device__ __forceinline__ void ldbT(uint32_t b[4], uint32_t tb, int kk, int nb2, int lane) {
    int sel = lane >> 3;
    int row = kk * 16 + ((sel & 1) << 3) + (lane & 7);
    int ch  = nb2 * 2 + (sel >> 1);
    ldsm4t(b, tb + swz(row, ch));
}
static __device__ __forceinline__ void mmaf16(float c[4], const uint32_t a[4], uint32_t b0, uint32_t b1) {
    asm volatile("mma.sync.aligned.m16n8k16.row.col.f32.f16.f16.f32 "
                 "{%0,%1,%2,%3}, {%4,%5,%6,%7}, {%8,%9}, {%0,%1,%2,%3};"
                 : "+f"(c[0]), "+f"(c[1]), "+f"(c[2]), "+f"(c[3])
                 : "r"(a[0]), "r"(a[1]), "r"(a[2]), "r"(a[3]), "r"(b0), "r"(b1));
}

__global__ __launch_bounds__(256, 2)
void attn_f16_kernel(const float* __restrict__ q,
                     const float* __restrict__ k,
                     const float* __restrict__ v,
                     const float* __restrict__ bias,
                     float* __restrict__ out)
{
    extern __shared__ char smem[];
    const uint32_t sb = smem_u32(smem);
    const int tid  = threadIdx.x;
    const int wid  = tid >> 5;
    const int lane = tid & 31;
    const int qd   = lane & 3;

    const int m  = 7 - (int)(blockIdx.x >> 6);   // heavy CTAs first
    const int bh = (int)(blockIdx.x & 63);

    // ---- prologue: stage Q (scaled, fp16 hi/lo split) ----
    const float* qp = q + ((size_t)bh * SEQ + (size_t)m * BM) * 64;
    #pragma unroll
    for (int i = 0; i < 8; ++i) {
        int lin = tid + i * 256;
        int row = lin >> 4;
        int d4  = (lin & 15) * 4;
        float4 v4 = *reinterpret_cast<const float4*>(qp + row * 64 + d4);
        float xs[4] = {v4.x * 0.125f, v4.y * 0.125f, v4.z * 0.125f, v4.w * 0.125f};
        float h[4], l[4];
        #pragma unroll
        for (int e = 0; e < 4; ++e) {
            __half hh = __float2half_rn(xs[e]);
            h[e] = __half2float(hh);
            l[e] = xs[e] - h[e];
        }
        uint32_t off = swz(row, d4 >> 3) + (uint32_t)((d4 & 7) * 2);
        *reinterpret_cast<uint2*>(smem + SM_QH + off) = make_uint2(hpair(h[0], h[1]), hpair(h[2], h[3]));
        *reinterpret_cast<uint2*>(smem + SM_QL + off) = make_uint2(hpair(l[0], l[1]), hpair(l[2], l[3]));
    }

    const int wr0 = wid * 16;
    const int gra = m * BM + wr0 + (lane >> 2);
    const int grb = gra + 8;

    float s[8][4];
    float o[8][4];
    #pragma unroll
    for (int nb = 0; nb < 8; ++nb)
        #pragma unroll
        for (int e = 0; e < 4; ++e) o[nb][e] = 0.f;
    float m_a = -INFINITY, m_b = -INFINITY, l_a = 0.f, l_b = 0.f;

    const int wlast = m * BM + wr0 + 15;
    const int nsup  = m + 1;              // 128-key super-tiles

    for (int nt = 0; nt < nsup; ++nt) {
        // ---- stage 128-key K/V super-tile into buffer nt&1 (compact block) ----
        const uint32_t kvb = SM_KV + (uint32_t)(nt & 1) * KVSZ;
        const float* kp = k + ((size_t)bh * SEQ + (size_t)nt * 128) * 64;
        const float* vp = v + ((size_t)bh * SEQ + (size_t)nt * 128) * 64;
        #pragma unroll
        for (int i = 0; i < 8; ++i) {
            int lin = tid + i * 256;
            int row = lin >> 4;               // 0..127
            int d4  = (lin & 15) * 4;
            uint32_t off = swz(row, d4 >> 3) + (uint32_t)((d4 & 7) * 2);
            float4 kv = *reinterpret_cast<const float4*>(kp + row * 64 + d4);
            *reinterpret_cast<uint2*>(smem + kvb + KV_K + off) =
                make_uint2(hpair(kv.x, kv.y), hpair(kv.z, kv.w));
            float4 vv = *reinterpret_cast<const float4*>(vp + row * 64 + d4);
            *reinterpret_cast<uint2*>(smem + kvb + KV_V + off) =
                make_uint2(hpair(vv.x, vv.y), hpair(vv.z, vv.w));
        }
        __syncthreads();   // single barrier per super-tile

        #pragma unroll
        for (int half = 0; half < 2; ++half) {
            const int n = nt * 2 + half;     // 64-key block index (same order as before)
            const bool active = (n * BKT <= wlast);
            if (!active) continue;

            // rows 64..127 of the buffer are at +8192 bytes (64 % 8 == 0)
            const uint32_t KB = sb + kvb + KV_K + (uint32_t)half * 8192u;
            const uint32_t VB = sb + kvb + KV_V + (uint32_t)half * 8192u;

            // bias prefetch (hides under QK MMAs)
            float2 ba[8], bb[8];
            {
                const float* bpa = bias + ((size_t)bh * SEQ + gra) * SEQ + (size_t)n * BKT;
                const float* bpb = bias + ((size_t)bh * SEQ + grb) * SEQ + (size_t)n * BKT;
                #pragma unroll
                for (int nb = 0; nb < 8; ++nb) {
                    ba[nb] = *reinterpret_cast<const float2*>(bpa + nb * 8 + 2 * qd);
                    bb[nb] = *reinterpret_cast<const float2*>(bpb + nb * 8 + 2 * qd);
                }
            }

            // ---- S = Qh*K + Ql*K ----
            #pragma unroll
            for (int nb = 0; nb < 8; ++nb)
                #pragma unroll
                for (int e = 0; e < 4; ++e) s[nb][e] = 0.f;
            #pragma unroll
            for (int kk = 0; kk < 4; ++kk) {
                uint32_t aqh[4], aql[4];
                lda(aqh, sb + SM_QH, wr0, kk, lane);
                lda(aql, sb + SM_QL, wr0, kk, lane);
                #pragma unroll
                for (int nb2 = 0; nb2 < 4; ++nb2) {
                    uint32_t bk[4];
                    ldb(bk, KB, nb2 * 16, kk, lane);
                    mmaf16(s[2 * nb2],     aqh, bk[0], bk[1]);
                    mmaf16(s[2 * nb2 + 1], aqh, bk[2], bk[3]);
                    mmaf16(s[2 * nb2],     aql, bk[0], bk[1]);
                    mmaf16(s[2 * nb2 + 1], aql, bk[2], bk[3]);
                }
            }

            // ---- bias + causal mask ----
            const int c00 = n * BKT + 2 * qd;
            #pragma unroll
            for (int nb = 0; nb < 8; ++nb) {
                int c0 = c00 + nb * 8, c1 = c0 + 1;
                s[nb][0] = (c0 <= gra) ? s[nb][0] + ba[nb].x : -INFINITY;
                s[nb][1] = (c1 <= gra) ? s[nb][1] + ba[nb].y : -INFINITY;
                s[nb][2] = (c0 <= grb) ? s[nb][2] + bb[nb].x : -INFINITY;
                s[nb][3] = (c1 <= grb) ? s[nb][3] + bb[nb].y : -INFINITY;
            }

            // ---- online softmax ----
            float tma = -INFINITY, tmb = -INFINITY;
            #pragma unroll
            for (int nb = 0; nb < 8; ++nb) {
                tma = fmaxf(tma, fmaxf(s[nb][0], s[nb][1]));
                tmb = fmaxf(tmb, fmaxf(s[nb][2], s[nb][3]));
            }
            tma = fmaxf(tma, __shfl_xor_sync(0xffffffffu, tma, 1));
            tma = fmaxf(tma, __shfl_xor_sync(0xffffffffu, tma, 2));
            tmb = fmaxf(tmb, __shfl_xor_sync(0xffffffffu, tmb, 1));
            tmb = fmaxf(tmb, __shfl_xor_sync(0xffffffffu, tmb, 2));

            float mna = fmaxf(m_a, tma), mnb = fmaxf(m_b, tmb);
            float ca = __expf(m_a - mna), cb = __expf(m_b - mnb);
            m_a = mna; m_b = mnb;

            float pa = 0.f, pb = 0.f;
            #pragma unroll
            for (int nb = 0; nb < 8; ++nb) {
                float p0 = __expf(s[nb][0] - mna);
                float p1 = __expf(s[nb][1] - mna);
                float p2 = __expf(s[nb][2] - mnb);
                float p3 = __expf(s[nb][3] - mnb);
                s[nb][0] = p0; s[nb][1] = p1; s[nb][2] = p2; s[nb][3] = p3;
                pa += p0 + p1; pb += p2 + p3;
            }
            pa += __shfl_xor_sync(0xffffffffu, pa, 1);
            pa += __shfl_xor_sync(0xffffffffu, pa, 2);
            pb += __shfl_xor_sync(0xffffffffu, pb, 1);
            pb += __shfl_xor_sync(0xffffffffu, pb, 2);
            l_a = l_a * ca + pa;
            l_b = l_b * cb + pb;
            #pragma unroll
            for (int nb = 0; nb < 8; ++nb) {
                o[nb][0] *= ca; o[nb][1] *= ca;
                o[nb][2] *= cb; o[nb][3] *= cb;
            }

            // ---- O += Ph*V + Pl*V (P hi/lo fp16 straight from S regs) ----
            #pragma unroll
            for (int kk = 0; kk < 4; ++kk) {
                uint32_t aph[4], apl[4];
                #pragma unroll
                for (int hf = 0; hf < 2; ++hf) {
                    const float* sp = s[2 * kk + hf];
                    float h[4], l[4];
                    #pragma unroll
                    for (int e = 0; e < 4; ++e) {
                        __half hh = __float2half_rn(sp[e]);
                        h[e] = __half2float(hh);
                        l[e] = sp[e] - h[e];
                    }
                    aph[2 * hf]     = hpair(h[0], h[1]);
                    aph[2 * hf + 1] = hpair(h[2], h[3]);
                    apl[2 * hf]     = hpair(l[0], l[1]);
                    apl[2 * hf + 1] = hpair(l[2], l[3]);
                }
                #pragma unroll
                for (int nb2 = 0; nb2 < 4; ++nb2) {
                    uint32_t bv[4];
                    ldbT(bv, VB, kk, nb2, lane);
                    mmaf16(o[2 * nb2],     aph, bv[0], bv[1]);
                    mmaf16(o[2 * nb2 + 1], aph, bv[2], bv[3]);
                    mmaf16(o[2 * nb2],     apl, bv[0], bv[1]);
                    mmaf16(o[2 * nb2 + 1], apl, bv[2], bv[3]);
                }
            }
        }
    }

    // ---- epilogue ----
    const float ia = 1.f / l_a, ib = 1.f / l_b;
    float* opa = out + ((size_t)bh * SEQ + gra) * 64;
    float* opb = out + ((size_t)bh * SEQ + grb) * 64;
    #pragma unroll
    for (int nb = 0; nb < 8; ++nb) {
        int col = nb * 8 + 2 * qd;
        *reinterpret_cast<float2*>(opa + col) = make_float2(o[nb][0] * ia, o[nb][1] * ia);
        *reinterpret_cast<float2*>(opb + col) = make_float2(o[nb][2] * ib, o[nb][3] * ib);
    }
}

extern "C" void kernel_launch(void* const* d_in, const int* in_sizes, int n_in,
                              void* d_out, int out_size)
{
    const float* q    = (const float*)d_in[0];
    const float* k    = (const float*)d_in[1];
    const float* v    = (const float*)d_in[2];
    const float* bias = (const float*)d_in[3];
    float* out = (float*)d_out;

    cudaFuncSetAttribute(attn_f16_kernel,
                         cudaFuncAttributeMaxDynamicSharedMemorySize, SM_TOTAL);
    attn_f16_kernel<<<512, 256, SM_TOTAL>>>(q, k, v, bias, out);
}

// round 14
// speedup vs baseline: 1.5864x; 1.1041x over previous
#include <cuda_runtime.h>
#include <cuda_fp16.h>
#include <math.h>
#include <stdint.h>

// Flash attention w/ bias + causal, fp32 I/O, fp16 mma.sync (m16n8k16).
// 2 CTAs/SM, 72KB smem, 128-reg cap. Affine 144B-stride smem (no XOR swizzle,
// conflict-free for ldmatrix, immediate-offset addressing), exp2-domain softmax,
// warp-uniform fast path for non-diagonal tiles.
// QK = Qh*K + Ql*K ; PV = Ph*V + Pl*V (P hi/lo fp16 from S-regs).

#define SEQ 1024
#define BM  128
#define BKT 64
#define RS  144                  // smem row stride bytes (128 data + 16 pad)

#define SM_QH  0u
#define SM_QL  18432u
#define SM_KV  36864u
#define KVSZ   18432u
#define KV_K   0u
#define KV_V   9216u
#define SM_TOTAL 73728

#define SCALE_L2E 0.18033688011112042f   // 0.125 * log2(e)
#define LOG2E     1.4426950408889634f

static __device__ __forceinline__ uint32_t smem_u32(const void* p) {
    uint32_t a;
    asm("{ .reg .u64 t; cvta.to.shared.u64 t, %1; cvt.u32.u64 %0, t; }" : "=r"(a) : "l"(p));
    return a;
}
static __device__ __forceinline__ float ex2(float x) {
    float r; asm("ex2.approx.f32 %0, %1;" : "=f"(r) : "f"(x));
    return r;
}
static __device__ __forceinline__ uint32_t hpair(float a, float b) {
    __half2 t = __floats2half2_rn(a, b);
    return *reinterpret_cast<uint32_t*>(&t);
}
static __device__ __forceinline__ void ldsm4(uint32_t r[4], uint32_t addr) {
    asm volatile("ldmatrix.sync.aligned.m8n8.x4.shared.b16 {%0,%1,%2,%3}, [%4];"
                 : "=r"(r[0]), "=r"(r[1]), "=r"(r[2]), "=r"(r[3]) : "r"(addr));
}
static __device__ __forceinline__ void ldsm4t(uint32_t r[4], uint32_t addr) {
    asm volatile("ldmatrix.sync.aligned.m8n8.x4.trans.shared.b16 {%0,%1,%2,%3}, [%4];"
                 : "=r"(r[0]), "=r"(r[1]), "=r"(r[2]), "=r"(r[3]) : "r"(addr));
}
static __device__ __forceinline__ void mmaf16(float c[4], const uint32_t a[4], uint32_t b0, uint32_t b1) {
    asm volatile("mma.sync.aligned.m16n8k16.row.col.f32.f16.f16.f32 "
                 "{%0,%1,%2,%3}, {%4,%5,%6,%7}, {%8,%9}, {%0,%1,%2,%3};"
                 : "+f"(c[0]), "+f"(c[1]), "+f"(c[2]), "+f"(c[3])
                 : "r"(a[0]), "r"(a[1]), "r"(a[2]), "r"(a[3]), "r"(b0), "r"(b1));
}

__global__ __launch_bounds__(256, 2)
void attn_f16_kernel(const float* __restrict__ q,
                     const float* __restrict__ k,
                     const float* __restrict__ v,
                     const float* __restrict__ bias,
                     float* __restrict__ out)
{
    extern __shared__ char smem[];
    const uint32_t sb = smem_u32(smem);
    const int tid  = threadIdx.x;
    const int wid  = tid >> 5;
    const int lane = tid & 31;
    const int qd   = lane & 3;
    const int sel  = lane >> 3;

    const int m  = 7 - (int)(blockIdx.x >> 6);   // heavy CTAs first
    const int bh = (int)(blockIdx.x & 63);

    // ---- prologue: stage Q (scaled by 0.125*log2e, fp16 hi/lo split) ----
    const float* qp = q + ((size_t)bh * SEQ + (size_t)m * BM) * 64;
    #pragma unroll
    for (int i = 0; i < 8; ++i) {
        int lin = tid + i * 256;
        int row = lin >> 4;
        int d4  = (lin & 15) * 4;
        float4 v4 = *reinterpret_cast<const float4*>(qp + row * 64 + d4);
        float xs[4] = {v4.x * SCALE_L2E, v4.y * SCALE_L2E,
                       v4.z * SCALE_L2E, v4.w * SCALE_L2E};
        float h[4], l[4];
        #pragma unroll
        for (int e = 0; e < 4; ++e) {
            __half hh = __float2half_rn(xs[e]);
            h[e] = __half2float(hh);
            l[e] = xs[e] - h[e];
        }
        uint32_t off = (uint32_t)(row * RS + (lin & 15) * 8);
        *reinterpret_cast<uint2*>(smem + SM_QH + off) = make_uint2(hpair(h[0], h[1]), hpair(h[2], h[3]));
        *reinterpret_cast<uint2*>(smem + SM_QL + off) = make_uint2(hpair(l[0], l[1]), hpair(l[2], l[3]));
    }

    const int wr0 = wid * 16;
    const int gra = m * BM + wr0 + (lane >> 2);
    const int grb = gra + 8;

    // loop-invariant fragment base addresses (immediate offsets added per call)
    const uint32_t aoff = (uint32_t)((wr0 + (lane & 7) + ((sel & 1) << 3)) * RS + (sel >> 1) * 16);
    const uint32_t qhb  = sb + SM_QH + aoff;
    const uint32_t qlb  = sb + SM_QL + aoff;
    const uint32_t boff = (uint32_t)((((sel >> 1) << 3) + (lane & 7)) * RS + (sel & 1) * 16);
    const uint32_t voff = (uint32_t)((((sel & 1) << 3) + (lane & 7)) * RS + (sel >> 1) * 16);

    float s[8][4];
    float o[8][4];
    #pragma unroll
    for (int nb = 0; nb < 8; ++nb)
        #pragma unroll
        for (int e = 0; e < 4; ++e) o[nb][e] = 0.f;
    float m_a = -INFINITY, m_b = -INFINITY, l_a = 0.f, l_b = 0.f;

    const int ntiles = 2 * m + 2;
    const int wlast  = m * BM + wr0 + 15;

    for (int n = 0; n < ntiles; ++n) {
        // ---- stage K and V (single fp16) into buffer n&1 ----
        const uint32_t kvb = SM_KV + (uint32_t)(n & 1) * KVSZ;
        const float* kp = k + ((size_t)bh * SEQ + (size_t)n * BKT) * 64;
        const float* vp = v + ((size_t)bh * SEQ + (size_t)n * BKT) * 64;
        #pragma unroll
        for (int i = 0; i < 4; ++i) {
            int lin = tid + i * 256;
            int row = lin >> 4;
            uint32_t off = (uint32_t)(row * RS + (lin & 15) * 8);
            int d4 = (lin & 15) * 4;
            float4 kv = *reinterpret_cast<const float4*>(kp + row * 64 + d4);
            *reinterpret_cast<uint2*>(smem + kvb + KV_K + off) =
                make_uint2(hpair(kv.x, kv.y), hpair(kv.z, kv.w));
            float4 vv = *reinterpret_cast<const float4*>(vp + row * 64 + d4);
            *reinterpret_cast<uint2*>(smem + kvb + KV_V + off) =
                make_uint2(hpair(vv.x, vv.y), hpair(vv.z, vv.w));
        }
        __syncthreads();   // single barrier per tile

        const bool active = (n * BKT <= wlast);
        if (active) {
            const uint32_t KB = sb + kvb + KV_K + boff;
            const uint32_t VB = sb + kvb + KV_V + voff;

            // bias prefetch, scaled to log2 domain (hides under QK MMAs)
            float2 ba[8], bb[8];
            {
                const float* bpa = bias + ((size_t)bh * SEQ + gra) * SEQ + (size_t)n * BKT;
                const float* bpb = bias + ((size_t)bh * SEQ + grb) * SEQ + (size_t)n * BKT;
                #pragma unroll
                for (int nb = 0; nb < 8; ++nb) {
                    ba[nb] = *reinterpret_cast<const float2*>(bpa + nb * 8 + 2 * qd);
                    bb[nb] = *reinterpret_cast<const float2*>(bpb + nb * 8 + 2 * qd);
                    ba[nb].x *= LOG2E; ba[nb].y *= LOG2E;
                    bb[nb].x *= LOG2E; bb[nb].y *= LOG2E;
                }
            }

            // ---- S = Qh*K + Ql*K (immediate-offset ldsm) ----
            #pragma unroll
            for (int nb = 0; nb < 8; ++nb)
                #pragma unroll
                for (int e = 0; e < 4; ++e) s[nb][e] = 0.f;
            #pragma unroll
            for (int kk = 0; kk < 4; ++kk) {
                uint32_t aqh[4], aql[4];
                ldsm4(aqh, qhb + (uint32_t)(kk * 32));
                ldsm4(aql, qlb + (uint32_t)(kk * 32));
                #pragma unroll
                for (int nb2 = 0; nb2 < 4; ++nb2) {
                    uint32_t bk[4];
                    ldsm4(bk, KB + (uint32_t)(nb2 * 16 * RS + kk * 32));
                    mmaf16(s[2 * nb2],     aqh, bk[0], bk[1]);
                    mmaf16(s[2 * nb2 + 1], aqh, bk[2], bk[3]);
                    mmaf16(s[2 * nb2],     aql, bk[0], bk[1]);
                    mmaf16(s[2 * nb2 + 1], aql, bk[2], bk[3]);
                }
            }

            // ---- bias add (+ causal mask only on diagonal tiles) ----
            if (n * BKT + BKT - 1 <= m * BM + wr0) {
                // fully-visible tile: no mask checks
                #pragma unroll
                for (int nb = 0; nb < 8; ++nb) {
                    s[nb][0] += ba[nb].x; s[nb][1] += ba[nb].y;
                    s[nb][2] += bb[nb].x; s[nb][3] += bb[nb].y;
                }
            } else {
                const int c00 = n * BKT + 2 * qd;
                #pragma unroll
                for (int nb = 0; nb < 8; ++nb) {
                    int c0 = c00 + nb * 8, c1 = c0 + 1;
                    s[nb][0] = (c0 <= gra) ? s[nb][0] + ba[nb].x : -INFINITY;
                    s[nb][1] = (c1 <= gra) ? s[nb][1] + ba[nb].y : -INFINITY;
                    s[nb][2] = (c0 <= grb) ? s[nb][2] + bb[nb].x : -INFINITY;
                    s[nb][3] = (c1 <= grb) ? s[nb][3] + bb[nb].y : -INFINITY;
                }
            }

            // ---- online softmax (log2 domain) ----
            float tma = -INFINITY, tmb = -INFINITY;
            #pragma unroll
            for (int nb = 0; nb < 8; ++nb) {
                tma = fmaxf(tma, fmaxf(s[nb][0], s[nb][1]));
                tmb = fmaxf(tmb, fmaxf(s[nb][2], s[nb][3]));
            }
            tma = fmaxf(tma, __shfl_xor_sync(0xffffffffu, tma, 1));
            tma = fmaxf(tma, __shfl_xor_sync(0xffffffffu, tma, 2));
            tmb = fmaxf(tmb, __shfl_xor_sync(0xffffffffu, tmb, 1));
            tmb = fmaxf(tmb, __shfl_xor_sync(0xffffffffu, tmb, 2));

            float mna = fmaxf(m_a, tma), mnb = fmaxf(m_b, tmb);
            float ca = ex2(m_a - mna), cb = ex2(m_b - mnb);
            m_a = mna; m_b = mnb;

            float pa = 0.f, pb = 0.f;
            #pragma unroll
            for (int nb = 0; nb < 8; ++nb) {
                float p0 = ex2(s[nb][0] - mna);
                float p1 = ex2(s[nb][1] - mna);
                float p2 = ex2(s[nb][2] - mnb);
                float p3 = ex2(s[nb][3] - mnb);
                s[nb][0] = p0; s[nb][1] = p1; s[nb][2] = p2; s[nb][3] = p3;
                pa += p0 + p1; pb += p2 + p3;
            }
            pa += __shfl_xor_sync(0xffffffffu, pa, 1);
            pa += __shfl_xor_sync(0xffffffffu, pa, 2);
            pb += __shfl_xor_sync(0xffffffffu, pb, 1);
            pb += __shfl_xor_sync(0xffffffffu, pb, 2);
            l_a = l_a * ca + pa;
            l_b = l_b * cb + pb;
            #pragma unroll
            for (int nb = 0; nb < 8; ++nb) {
                o[nb][0] *= ca; o[nb][1] *= ca;
                o[nb][2] *= cb; o[nb][3] *= cb;
            }

            // ---- O += Ph*V + Pl*V (P hi/lo fp16 straight from S regs) ----
            #pragma unroll
            for (int kk = 0; kk < 4; ++kk) {
                uint32_t aph[4], apl[4];
                #pragma unroll
                for (int hf = 0; hf < 2; ++hf) {
                    const float* sp = s[2 * kk + hf];
                    float h[4], l[4];
                    #pragma unroll
                    for (int e = 0; e < 4; ++e) {
                        __half hh = __float2half_rn(sp[e]);
                        h[e] = __half2float(hh);
                        l[e] = sp[e] - h[e];
                    }
                    aph[2 * hf]     = hpair(h[0], h[1]);
                    aph[2 * hf + 1] = hpair(h[2], h[3]);
                    apl[2 * hf]     = hpair(l[0], l[1]);
                    apl[2 * hf + 1] = hpair(l[2], l[3]);
                }
                #pragma unroll
                for (int nb2 = 0; nb2 < 4; ++nb2) {
                    uint32_t bv[4];
                    ldsm4t(bv, VB + (uint32_t)(kk * 16 * RS + nb2 * 32));
                    mmaf16(o[2 * nb2],     aph, bv[0], bv[1]);
                    mmaf16(o[2 * nb2 + 1], aph, bv[2], bv[3]);
                    mmaf16(o[2 * nb2],     apl, bv[0], bv[1]);
                    mmaf16(o[2 * nb2 + 1], apl, bv[2], bv[3]);
                }
            }
        }
    }

    // ---- epilogue ----
    const float ia = 1.f / l_a, ib = 1.f / l_b;
    float* opa = out + ((size_t)bh * SEQ + gra) * 64;
    float* opb = out + ((size_t)bh * SEQ + grb) * 64;
    #pragma unroll
    for (int nb = 0; nb < 8; ++nb) {
        int col = nb * 8 + 2 * qd;
        *reinterpret_cast<float2*>(opa + col) = make_float2(o[nb][0] * ia, o[nb][1] * ia);
        *reinterpret_cast<float2*>(opb + col) = make_float2(o[nb][2] * ib, o[nb][3] * ib);
    }
}

extern "C" void kernel_launch(void* const* d_in, const int* in_sizes, int n_in,
                              void* d_out, int out_size)
{
    const float* q    = (const float*)d_in[0];
    const float* k    = (const float*)d_in[1];
    const float* v    = (const float*)d_in[2];
    const float* bias = (const float*)d_in[3];
    float* out = (float*)d_out;

    cudaFuncSetAttribute(attn_f16_kernel,
                         cudaFuncAttributeMaxDynamicSharedMemorySize, SM_TOTAL);
    attn_f16_kernel<<<512, 256, SM_TOTAL>>>(q, k, v, bias, out);
}

// round 15
// speedup vs baseline: 1.6820x; 1.0603x over previous
#include <cuda_runtime.h>
#include <cuda_fp16.h>
#include <math.h>
#include <stdint.h>

// Flash attention w/ bias + causal, fp32 I/O, fp16 mma.sync (m16n8k16).
// 2 CTAs/SM, 72KB smem, 128-reg cap. Affine 144B-stride smem, exp2 softmax,
// single-pass PV (P fp16 straight from S-regs), masked-group skipping on
// diagonal tiles. QK = Qh*K + Ql*K ; PV = P*V.

#define SEQ 1024
#define BM  128
#define BKT 64
#define RS  144                  // smem row stride bytes (128 data + 16 pad)

#define SM_QH  0u
#define SM_QL  18432u
#define SM_KV  36864u
#define KVSZ   18432u
#define KV_K   0u
#define KV_V   9216u
#define SM_TOTAL 73728

#define SCALE_L2E 0.18033688011112042f   // 0.125 * log2(e)
#define LOG2E     1.4426950408889634f

static __device__ __forceinline__ uint32_t smem_u32(const void* p) {
    uint32_t a;
    asm("{ .reg .u64 t; cvta.to.shared.u64 t, %1; cvt.u32.u64 %0, t; }" : "=r"(a) : "l"(p));
    return a;
}
static __device__ __forceinline__ float ex2(float x) {
    float r; asm("ex2.approx.f32 %0, %1;" : "=f"(r) : "f"(x));
    return r;
}
static __device__ __forceinline__ uint32_t hpair(float a, float b) {
    __half2 t = __floats2half2_rn(a, b);
    return *reinterpret_cast<uint32_t*>(&t);
}
static __device__ __forceinline__ void ldsm4(uint32_t r[4], uint32_t addr) {
    asm volatile("ldmatrix.sync.aligned.m8n8.x4.shared.b16 {%0,%1,%2,%3}, [%4];"
                 : "=r"(r[0]), "=r"(r[1]), "=r"(r[2]), "=r"(r[3]) : "r"(addr));
}
static __device__ __forceinline__ void ldsm4t(uint32_t r[4], uint32_t addr) {
    asm volatile("ldmatrix.sync.aligned.m8n8.x4.trans.shared.b16 {%0,%1,%2,%3}, [%4];"
                 : "=r"(r[0]), "=r"(r[1]), "=r"(r[2]), "=r"(r[3]) : "r"(addr));
}
static __device__ __forceinline__ void mmaf16(float c[4], const uint32_t a[4], uint32_t b0, uint32_t b1) {
    asm volatile("mma.sync.aligned.m16n8k16.row.col.f32.f16.f16.f32 "
                 "{%0,%1,%2,%3}, {%4,%5,%6,%7}, {%8,%9}, {%0,%1,%2,%3};"
                 : "+f"(c[0]), "+f"(c[1]), "+f"(c[2]), "+f"(c[3])
                 : "r"(a[0]), "r"(a[1]), "r"(a[2]), "r"(a[3]), "r"(b0), "r"(b1));
}

__global__ __launch_bounds__(256, 2)
void attn_f16_kernel(const float* __restrict__ q,
                     const float* __restrict__ k,
                     const float* __restrict__ v,
                     const float* __restrict__ bias,
                     float* __restrict__ out)
{
    extern __shared__ char smem[];
    const uint32_t sb = smem_u32(smem);
    const int tid  = threadIdx.x;
    const int wid  = tid >> 5;
    const int lane = tid & 31;
    const int qd   = lane & 3;
    const int sel  = lane >> 3;

    const int m  = 7 - (int)(blockIdx.x >> 6);   // heavy CTAs first
    const int bh = (int)(blockIdx.x & 63);

    // ---- prologue: stage Q (scaled by 0.125*log2e, fp16 hi/lo split) ----
    const float* qp = q + ((size_t)bh * SEQ + (size_t)m * BM) * 64;
    #pragma unroll
    for (int i = 0; i < 8; ++i) {
        int lin = tid + i * 256;
        int row = lin >> 4;
        int d4  = (lin & 15) * 4;
        float4 v4 = *reinterpret_cast<const float4*>(qp + row * 64 + d4);
        float xs[4] = {v4.x * SCALE_L2E, v4.y * SCALE_L2E,
                       v4.z * SCALE_L2E, v4.w * SCALE_L2E};
        float h[4], l[4];
        #pragma unroll
        for (int e = 0; e < 4; ++e) {
            __half hh = __float2half_rn(xs[e]);
            h[e] = __half2float(hh);
            l[e] = xs[e] - h[e];
        }
        uint32_t off = (uint32_t)(row * RS + (lin & 15) * 8);
        *reinterpret_cast<uint2*>(smem + SM_QH + off) = make_uint2(hpair(h[0], h[1]), hpair(h[2], h[3]));
        *reinterpret_cast<uint2*>(smem + SM_QL + off) = make_uint2(hpair(l[0], l[1]), hpair(l[2], l[3]));
    }

    const int wr0 = wid * 16;
    const int gra = m * BM + wr0 + (lane >> 2);
    const int grb = gra + 8;

    // loop-invariant fragment base addresses
    const uint32_t aoff = (uint32_t)((wr0 + (lane & 7) + ((sel & 1) << 3)) * RS + (sel >> 1) * 16);
    const uint32_t qhb  = sb + SM_QH + aoff;
    const uint32_t qlb  = sb + SM_QL + aoff;
    const uint32_t boff = (uint32_t)((((sel >> 1) << 3) + (lane & 7)) * RS + (sel & 1) * 16);
    const uint32_t voff = (uint32_t)((((sel & 1) << 3) + (lane & 7)) * RS + (sel >> 1) * 16);

    float s[8][4];
    float o[8][4];
    #pragma unroll
    for (int nb = 0; nb < 8; ++nb)
        #pragma unroll
        for (int e = 0; e < 4; ++e) o[nb][e] = 0.f;
    float m_a = -INFINITY, m_b = -INFINITY, l_a = 0.f, l_b = 0.f;

    const int ntiles = 2 * m + 2;
    const int wlast  = m * BM + wr0 + 15;

    for (int n = 0; n < ntiles; ++n) {
        // ---- stage K and V (single fp16) into buffer n&1 ----
        const uint32_t kvb = SM_KV + (uint32_t)(n & 1) * KVSZ;
        const float* kp = k + ((size_t)bh * SEQ + (size_t)n * BKT) * 64;
        const float* vp = v + ((size_t)bh * SEQ + (size_t)n * BKT) * 64;
        #pragma unroll
        for (int i = 0; i < 4; ++i) {
            int lin = tid + i * 256;
            int row = lin >> 4;
            uint32_t off = (uint32_t)(row * RS + (lin & 15) * 8);
            int d4 = (lin & 15) * 4;
            float4 kv = *reinterpret_cast<const float4*>(kp + row * 64 + d4);
            *reinterpret_cast<uint2*>(smem + kvb + KV_K + off) =
                make_uint2(hpair(kv.x, kv.y), hpair(kv.z, kv.w));
            float4 vv = *reinterpret_cast<const float4*>(vp + row * 64 + d4);
            *reinterpret_cast<uint2*>(smem + kvb + KV_V + off) =
                make_uint2(hpair(vv.x, vv.y), hpair(vv.z, vv.w));
        }
        __syncthreads();   // single barrier per tile

        const bool active = (n * BKT <= wlast);
        if (active) {
            const uint32_t KB = sb + kvb + KV_K + boff;
            const uint32_t VB = sb + kvb + KV_V + voff;
            const bool fullvis = (n * BKT + BKT - 1 <= m * BM + wr0);

            // per-16-key-group visibility (warp-uniform); all true on full tiles
            bool vis[4];
            #pragma unroll
            for (int g = 0; g < 4; ++g)
                vis[g] = fullvis || (n * BKT + g * 16 <= wlast);

            // bias prefetch, scaled to log2 domain (hides under QK MMAs)
            float2 ba[8], bb[8];
            {
                const float* bpa = bias + ((size_t)bh * SEQ + gra) * SEQ + (size_t)n * BKT;
                const float* bpb = bias + ((size_t)bh * SEQ + grb) * SEQ + (size_t)n * BKT;
                #pragma unroll
                for (int nb = 0; nb < 8; ++nb) {
                    ba[nb] = *reinterpret_cast<const float2*>(bpa + nb * 8 + 2 * qd);
                    bb[nb] = *reinterpret_cast<const float2*>(bpb + nb * 8 + 2 * qd);
                    ba[nb].x *= LOG2E; ba[nb].y *= LOG2E;
                    bb[nb].x *= LOG2E; bb[nb].y *= LOG2E;
                }
            }

            // ---- S = Qh*K + Ql*K (skip fully-masked groups) ----
            #pragma unroll
            for (int nb = 0; nb < 8; ++nb)
                #pragma unroll
                for (int e = 0; e < 4; ++e) s[nb][e] = 0.f;
            #pragma unroll
            for (int kk = 0; kk < 4; ++kk) {
                uint32_t aqh[4], aql[4];
                ldsm4(aqh, qhb + (uint32_t)(kk * 32));
                ldsm4(aql, qlb + (uint32_t)(kk * 32));
                #pragma unroll
                for (int nb2 = 0; nb2 < 4; ++nb2) {
                    if (vis[nb2]) {
                        uint32_t bk[4];
                        ldsm4(bk, KB + (uint32_t)(nb2 * 16 * RS + kk * 32));
                        mmaf16(s[2 * nb2],     aqh, bk[0], bk[1]);
                        mmaf16(s[2 * nb2 + 1], aqh, bk[2], bk[3]);
                        mmaf16(s[2 * nb2],     aql, bk[0], bk[1]);
                        mmaf16(s[2 * nb2 + 1], aql, bk[2], bk[3]);
                    }
                }
            }

            // ---- bias add (+ causal mask only on diagonal tiles) ----
            if (fullvis) {
                #pragma unroll
                for (int nb = 0; nb < 8; ++nb) {
                    s[nb][0] += ba[nb].x; s[nb][1] += ba[nb].y;
                    s[nb][2] += bb[nb].x; s[nb][3] += bb[nb].y;
                }
            } else {
                const int c00 = n * BKT + 2 * qd;
                #pragma unroll
                for (int nb = 0; nb < 8; ++nb) {
                    int c0 = c00 + nb * 8, c1 = c0 + 1;
                    s[nb][0] = (c0 <= gra) ? s[nb][0] + ba[nb].x : -INFINITY;
                    s[nb][1] = (c1 <= gra) ? s[nb][1] + ba[nb].y : -INFINITY;
                    s[nb][2] = (c0 <= grb) ? s[nb][2] + bb[nb].x : -INFINITY;
                    s[nb][3] = (c1 <= grb) ? s[nb][3] + bb[nb].y : -INFINITY;
                }
            }

            // ---- online softmax (log2 domain) ----
            float tma = -INFINITY, tmb = -INFINITY;
            #pragma unroll
            for (int nb = 0; nb < 8; ++nb) {
                tma = fmaxf(tma, fmaxf(s[nb][0], s[nb][1]));
                tmb = fmaxf(tmb, fmaxf(s[nb][2], s[nb][3]));
            }
            tma = fmaxf(tma, __shfl_xor_sync(0xffffffffu, tma, 1));
            tma = fmaxf(tma, __shfl_xor_sync(0xffffffffu, tma, 2));
            tmb = fmaxf(tmb, __shfl_xor_sync(0xffffffffu, tmb, 1));
            tmb = fmaxf(tmb, __shfl_xor_sync(0xffffffffu, tmb, 2));

            float mna = fmaxf(m_a, tma), mnb = fmaxf(m_b, tmb);
            float ca = ex2(m_a - mna), cb = ex2(m_b - mnb);
            m_a = mna; m_b = mnb;

            float pa = 0.f, pb = 0.f;
            #pragma unroll
            for (int nb = 0; nb < 8; ++nb) {
                float p0 = ex2(s[nb][0] - mna);
                float p1 = ex2(s[nb][1] - mna);
                float p2 = ex2(s[nb][2] - mnb);
                float p3 = ex2(s[nb][3] - mnb);
                s[nb][0] = p0; s[nb][1] = p1; s[nb][2] = p2; s[nb][3] = p3;
                pa += p0 + p1; pb += p2 + p3;
            }
            pa += __shfl_xor_sync(0xffffffffu, pa, 1);
            pa += __shfl_xor_sync(0xffffffffu, pa, 2);
            pb += __shfl_xor_sync(0xffffffffu, pb, 1);
            pb += __shfl_xor_sync(0xffffffffu, pb, 2);
            l_a = l_a * ca + pa;
            l_b = l_b * cb + pb;
            #pragma unroll
            for (int nb = 0; nb < 8; ++nb) {
                o[nb][0] *= ca; o[nb][1] *= ca;
                o[nb][2] *= cb; o[nb][3] *= cb;
            }

            // ---- O += P*V (single pass, P fp16 straight from S regs) ----
            #pragma unroll
            for (int kk = 0; kk < 4; ++kk) {
                if (vis[kk]) {
                    uint32_t ap[4];
                    #pragma unroll
                    for (int hf = 0; hf < 2; ++hf) {
                        const float* sp = s[2 * kk + hf];
                        ap[2 * hf]     = hpair(sp[0], sp[1]);
                        ap[2 * hf + 1] = hpair(sp[2], sp[3]);
                    }
                    #pragma unroll
                    for (int nb2 = 0; nb2 < 4; ++nb2) {
                        uint32_t bv[4];
                        ldsm4t(bv, VB + (uint32_t)(kk * 16 * RS + nb2 * 32));
                        mmaf16(o[2 * nb2],     ap, bv[0], bv[1]);
                        mmaf16(o[2 * nb2 + 1], ap, bv[2], bv[3]);
                    }
                }
            }
        }
    }

    // ---- epilogue ----
    const float ia = 1.f / l_a, ib = 1.f / l_b;
    float* opa = out + ((size_t)bh * SEQ + gra) * 64;
    float* opb = out + ((size_t)bh * SEQ + grb) * 64;
    #pragma unroll
    for (int nb = 0; nb < 8; ++nb) {
        int col = nb * 8 + 2 * qd;
        *reinterpret_cast<float2*>(opa + col) = make_float2(o[nb][0] * ia, o[nb][1] * ia);
        *reinterpret_cast<float2*>(opb + col) = make_float2(o[nb][2] * ib, o[nb][3] * ib);
    }
}

extern "C" void kernel_launch(void* const* d_in, const int* in_sizes, int n_in,
                              void* d_out, int out_size)
{
    const float* q    = (const float*)d_in[0];
    const float* k    = (const float*)d_in[1];
    const float* v    = (const float*)d_in[2];
    const float* bias = (const float*)d_in[3];
    float* out = (float*)d_out;

    cudaFuncSetAttribute(attn_f16_kernel,
                         cudaFuncAttributeMaxDynamicSharedMemorySize, SM_TOTAL);
    attn_f16_kernel<<<512, 256, SM_TOTAL>>>(q, k, v, bias, out);
}

// round 16
// speedup vs baseline: 1.7824x; 1.0597x over previous
#include <cuda_runtime.h>
#include <cuda_fp16.h>
#include <math.h>
#include <stdint.h>

// Flash attention w/ bias + causal, fp32 I/O, fp16 mma.sync (m16n8k16).
// 2 CTAs/SM, 54KB smem, 128-reg cap. Affine 144B-stride smem, exp2 softmax,
// single-pass QK (Q fp16) and single-pass PV (P fp16 from S-regs),
// masked-group skipping on diagonal tiles.

#define SEQ 1024
#define BM  128
#define BKT 64
#define RS  144                  // smem row stride bytes (128 data + 16 pad)

#define SM_QH  0u
#define SM_KV  18432u
#define KVSZ   18432u
#define KV_K   0u
#define KV_V   9216u
#define SM_TOTAL 55296

#define SCALE_L2E 0.18033688011112042f   // 0.125 * log2(e)
#define LOG2E     1.4426950408889634f

static __device__ __forceinline__ uint32_t smem_u32(const void* p) {
    uint32_t a;
    asm("{ .reg .u64 t; cvta.to.shared.u64 t, %1; cvt.u32.u64 %0, t; }" : "=r"(a) : "l"(p));
    return a;
}
static __device__ __forceinline__ float ex2(float x) {
    float r; asm("ex2.approx.f32 %0, %1;" : "=f"(r) : "f"(x));
    return r;
}
static __device__ __forceinline__ uint32_t hpair(float a, float b) {
    __half2 t = __floats2half2_rn(a, b);
    return *reinterpret_cast<uint32_t*>(&t);
}
static __device__ __forceinline__ void ldsm4(uint32_t r[4], uint32_t addr) {
    asm volatile("ldmatrix.sync.aligned.m8n8.x4.shared.b16 {%0,%1,%2,%3}, [%4];"
                 : "=r"(r[0]), "=r"(r[1]), "=r"(r[2]), "=r"(r[3]) : "r"(addr));
}
static __device__ __forceinline__ void ldsm4t(uint32_t r[4], uint32_t addr) {
    asm volatile("ldmatrix.sync.aligned.m8n8.x4.trans.shared.b16 {%0,%1,%2,%3}, [%4];"
                 : "=r"(r[0]), "=r"(r[1]), "=r"(r[2]), "=r"(r[3]) : "r"(addr));
}
static __device__ __forceinline__ void mmaf16(float c[4], const uint32_t a[4], uint32_t b0, uint32_t b1) {
    asm volatile("mma.sync.aligned.m16n8k16.row.col.f32.f16.f16.f32 "
                 "{%0,%1,%2,%3}, {%4,%5,%6,%7}, {%8,%9}, {%0,%1,%2,%3};"
                 : "+f"(c[0]), "+f"(c[1]), "+f"(c[2]), "+f"(c[3])
                 : "r"(a[0]), "r"(a[1]), "r"(a[2]), "r"(a[3]), "r"(b0), "r"(b1));
}

__global__ __launch_bounds__(256, 2)
void attn_f16_kernel(const float* __restrict__ q,
                     const float* __restrict__ k,
                     const float* __restrict__ v,
                     const float* __restrict__ bias,
                     float* __restrict__ out)
{
    extern __shared__ char smem[];
    const uint32_t sb = smem_u32(smem);
    const int tid  = threadIdx.x;
    const int wid  = tid >> 5;
    const int lane = tid & 31;
    const int qd   = lane & 3;
    const int sel  = lane >> 3;

    const int m  = 7 - (int)(blockIdx.x >> 6);   // heavy CTAs first
    const int bh = (int)(blockIdx.x & 63);

    // ---- prologue: stage Q (scaled by 0.125*log2e, single fp16) ----
    const float* qp = q + ((size_t)bh * SEQ + (size_t)m * BM) * 64;
    #pragma unroll
    for (int i = 0; i < 8; ++i) {
        int lin = tid + i * 256;
        int row = lin >> 4;
        int d4  = (lin & 15) * 4;
        float4 v4 = *reinterpret_cast<const float4*>(qp + row * 64 + d4);
        uint32_t off = (uint32_t)(row * RS + (lin & 15) * 8);
        *reinterpret_cast<uint2*>(smem + SM_QH + off) =
            make_uint2(hpair(v4.x * SCALE_L2E, v4.y * SCALE_L2E),
                       hpair(v4.z * SCALE_L2E, v4.w * SCALE_L2E));
    }

    const int wr0 = wid * 16;
    const int gra = m * BM + wr0 + (lane >> 2);
    const int grb = gra + 8;

    // loop-invariant fragment base addresses
    const uint32_t aoff = (uint32_t)((wr0 + (lane & 7) + ((sel & 1) << 3)) * RS + (sel >> 1) * 16);
    const uint32_t qhb  = sb + SM_QH + aoff;
    const uint32_t boff = (uint32_t)((((sel >> 1) << 3) + (lane & 7)) * RS + (sel & 1) * 16);
    const uint32_t voff = (uint32_t)((((sel & 1) << 3) + (lane & 7)) * RS + (sel >> 1) * 16);

    float s[8][4];
    float o[8][4];
    #pragma unroll
    for (int nb = 0; nb < 8; ++nb)
        #pragma unroll
        for (int e = 0; e < 4; ++e) o[nb][e] = 0.f;
    float m_a = -INFINITY, m_b = -INFINITY, l_a = 0.f, l_b = 0.f;

    const int ntiles = 2 * m + 2;
    const int wlast  = m * BM + wr0 + 15;

    for (int n = 0; n < ntiles; ++n) {
        // ---- stage K and V (single fp16) into buffer n&1 ----
        const uint32_t kvb = SM_KV + (uint32_t)(n & 1) * KVSZ;
        const float* kp = k + ((size_t)bh * SEQ + (size_t)n * BKT) * 64;
        const float* vp = v + ((size_t)bh * SEQ + (size_t)n * BKT) * 64;
        #pragma unroll
        for (int i = 0; i < 4; ++i) {
            int lin = tid + i * 256;
            int row = lin >> 4;
            uint32_t off = (uint32_t)(row * RS + (lin & 15) * 8);
            int d4 = (lin & 15) * 4;
            float4 kv = *reinterpret_cast<const float4*>(kp + row * 64 + d4);
            *reinterpret_cast<uint2*>(smem + kvb + KV_K + off) =
                make_uint2(hpair(kv.x, kv.y), hpair(kv.z, kv.w));
            float4 vv = *reinterpret_cast<const float4*>(vp + row * 64 + d4);
            *reinterpret_cast<uint2*>(smem + kvb + KV_V + off) =
                make_uint2(hpair(vv.x, vv.y), hpair(vv.z, vv.w));
        }
        __syncthreads();   // single barrier per tile

        const bool active = (n * BKT <= wlast);
        if (active) {
            const uint32_t KB = sb + kvb + KV_K + boff;
            const uint32_t VB = sb + kvb + KV_V + voff;
            const bool fullvis = (n * BKT + BKT - 1 <= m * BM + wr0);

            // per-16-key-group visibility (warp-uniform); all true on full tiles
            bool vis[4];
            #pragma unroll
            for (int g = 0; g < 4; ++g)
                vis[g] = fullvis || (n * BKT + g * 16 <= wlast);

            // bias prefetch, scaled to log2 domain (hides under QK MMAs)
            float2 ba[8], bb[8];
            {
                const float* bpa = bias + ((size_t)bh * SEQ + gra) * SEQ + (size_t)n * BKT;
                const float* bpb = bias + ((size_t)bh * SEQ + grb) * SEQ + (size_t)n * BKT;
                #pragma unroll
                for (int nb = 0; nb < 8; ++nb) {
                    ba[nb] = *reinterpret_cast<const float2*>(bpa + nb * 8 + 2 * qd);
                    bb[nb] = *reinterpret_cast<const float2*>(bpb + nb * 8 + 2 * qd);
                    ba[nb].x *= LOG2E; ba[nb].y *= LOG2E;
                    bb[nb].x *= LOG2E; bb[nb].y *= LOG2E;
                }
            }

            // ---- S = Q*K (single pass, skip fully-masked groups) ----
            #pragma unroll
            for (int nb = 0; nb < 8; ++nb)
                #pragma unroll
                for (int e = 0; e < 4; ++e) s[nb][e] = 0.f;
            #pragma unroll
            for (int kk = 0; kk < 4; ++kk) {
                uint32_t aq[4];
                ldsm4(aq, qhb + (uint32_t)(kk * 32));
                #pragma unroll
                for (int nb2 = 0; nb2 < 4; ++nb2) {
                    if (vis[nb2]) {
                        uint32_t bk[4];
                        ldsm4(bk, KB + (uint32_t)(nb2 * 16 * RS + kk * 32));
                        mmaf16(s[2 * nb2],     aq, bk[0], bk[1]);
                        mmaf16(s[2 * nb2 + 1], aq, bk[2], bk[3]);
                    }
                }
            }

            // ---- bias add (+ causal mask only on diagonal tiles) ----
            if (fullvis) {
                #pragma unroll
                for (int nb = 0; nb < 8; ++nb) {
                    s[nb][0] += ba[nb].x; s[nb][1] += ba[nb].y;
                    s[nb][2] += bb[nb].x; s[nb][3] += bb[nb].y;
                }
            } else {
                const int c00 = n * BKT + 2 * qd;
                #pragma unroll
                for (int nb = 0; nb < 8; ++nb) {
                    int c0 = c00 + nb * 8, c1 = c0 + 1;
                    s[nb][0] = (c0 <= gra) ? s[nb][0] + ba[nb].x : -INFINITY;
                    s[nb][1] = (c1 <= gra) ? s[nb][1] + ba[nb].y : -INFINITY;
                    s[nb][2] = (c0 <= grb) ? s[nb][2] + bb[nb].x : -INFINITY;
                    s[nb][3] = (c1 <= grb) ? s[nb][3] + bb[nb].y : -INFINITY;
                }
            }

            // ---- online softmax (log2 domain) ----
            float tma = -INFINITY, tmb = -INFINITY;
            #pragma unroll
            for (int nb = 0; nb < 8; ++nb) {
                tma = fmaxf(tma, fmaxf(s[nb][0], s[nb][1]));
                tmb = fmaxf(tmb, fmaxf(s[nb][2], s[nb][3]));
            }
            tma = fmaxf(tma, __shfl_xor_sync(0xffffffffu, tma, 1));
            tma = fmaxf(tma, __shfl_xor_sync(0xffffffffu, tma, 2));
            tmb = fmaxf(tmb, __shfl_xor_sync(0xffffffffu, tmb, 1));
            tmb = fmaxf(tmb, __shfl_xor_sync(0xffffffffu, tmb, 2));

            float mna = fmaxf(m_a, tma), mnb = fmaxf(m_b, tmb);
            float ca = ex2(m_a - mna), cb = ex2(m_b - mnb);
            m_a = mna; m_b = mnb;

            float pa = 0.f, pb = 0.f;
            #pragma unroll
            for (int nb = 0; nb < 8; ++nb) {
                float p0 = ex2(s[nb][0] - mna);
                float p1 = ex2(s[nb][1] - mna);
                float p2 = ex2(s[nb][2] - mnb);
                float p3 = ex2(s[nb][3] - mnb);
                s[nb][0] = p0; s[nb][1] = p1; s[nb][2] = p2; s[nb][3] = p3;
                pa += p0 + p1; pb += p2 + p3;
            }
            pa += __shfl_xor_sync(0xffffffffu, pa, 1);
            pa += __shfl_xor_sync(0xffffffffu, pa, 2);
            pb += __shfl_xor_sync(0xffffffffu, pb, 1);
            pb += __shfl_xor_sync(0xffffffffu, pb, 2);
            l_a = l_a * ca + pa;
            l_b = l_b * cb + pb;
            #pragma unroll
            for (int nb = 0; nb < 8; ++nb) {
                o[nb][0] *= ca; o[nb][1] *= ca;
                o[nb][2] *= cb; o[nb][3] *= cb;
            }

            // ---- O += P*V (single pass, P fp16 straight from S regs) ----
            #pragma unroll
            for (int kk = 0; kk < 4; ++kk) {
                if (vis[kk]) {
                    uint32_t ap[4];
                    #pragma unroll
                    for (int hf = 0; hf < 2; ++hf) {
                        const float* sp = s[2 * kk + hf];
                        ap[2 * hf]     = hpair(sp[0], sp[1]);
                        ap[2 * hf + 1] = hpair(sp[2], sp[3]);
                    }
                    #pragma unroll
                    for (int nb2 = 0; nb2 < 4; ++nb2) {
                        uint32_t bv[4];
                        ldsm4t(bv, VB + (uint32_t)(kk * 16 * RS + nb2 * 32));
                        mmaf16(o[2 * nb2],     ap, bv[0], bv[1]);
                        mmaf16(o[2 * nb2 + 1], ap, bv[2], bv[3]);
                    }
                }
            }
        }
    }

    // ---- epilogue ----
    const float ia = 1.f / l_a, ib = 1.f / l_b;
    float* opa = out + ((size_t)bh * SEQ + gra) * 64;
    float* opb = out + ((size_t)bh * SEQ + grb) * 64;
    #pragma unroll
    for (int nb = 0; nb < 8; ++nb) {
        int col = nb * 8 + 2 * qd;
        *reinterpret_cast<float2*>(opa + col) = make_float2(o[nb][0] * ia, o[nb][1] * ia);
        *reinterpret_cast<float2*>(opb + col) = make_float2(o[nb][2] * ib, o[nb][3] * ib);
    }
}

extern "C" void kernel_launch(void* const* d_in, const int* in_sizes, int n_in,
                              void* d_out, int out_size)
{
    const float* q    = (const float*)d_in[0];
    const float* k    = (const float*)d_in[1];
    const float* v    = (const float*)d_in[2];
    const float* bias = (const float*)d_in[3];
    float* out = (float*)d_out;

    cudaFuncSetAttribute(attn_f16_kernel,
                         cudaFuncAttributeMaxDynamicSharedMemorySize, SM_TOTAL);
    attn_f16_kernel<<<512, 256, SM_TOTAL>>>(q, k, v, bias, out);
}